// round 14
// baseline (speedup 1.0000x reference)
#include <cuda_runtime.h>
#include <mma.h>
#include <math.h>
#include <stdint.h>

using namespace nvcuda;

#define BB 256
#define SS 512
#define DD 32
#define HH 512
#define GG 2048   // 4*HH
#define PLEN 24
#define NB 128    // persistent blocks (<=148 SMs -> all co-resident)
#define TPB 512   // threads per block (16 warps)

#define XS 544    // xcat padded stride (544 = 17*32)
#define WD0K 1056 // Wd0 padded K (544 + 512)

// ---------------- scratch (__device__ globals; no allocation) ----------------
__device__ float g_enc_outs[BB * SS * HH];          // FULL fp32 h (stage D reads)
__device__ float g_enc_outs_r[BB * SS * HH];        // tf32-rounded h (enc_proj GEMM)
__device__ float g_enc_proj[BB * SS * HH];          // full fp32
__device__ float g_srcr[BB * SS * DD];              // tf32-rounded src copy
__device__ float g_attnW[HH * 2 * HH];              // tf32-rounded attn_W copy
__device__ float g_h0[2][BB * HH];                  // rounded (GEMM operand)
__device__ float g_h1[2][BB * HH];                  // rounded (GEMM operand)
__device__ float g_h1f[BB * HH];                    // FULL fp32 decoder h1 (stage G)
__device__ float g_c0[BB * HH];
__device__ float g_c1[BB * HH];
__device__ float g_W0[GG * 544];                    // [ew0 | eu0], gate-interleaved, tf32
__device__ float g_W1[GG * 1024];                   // [ew1 | eu1], tf32
__device__ float g_Wd0[GG * WD0K];                  // [dw0 | pad | du0], tf32
__device__ float g_Wd1[GG * 1024];                  // [dw1 | du1], tf32
__device__ float g_b0[GG], g_b1[GG], g_bd0[GG], g_bd1[GG];
__device__ float g_dp[BB * HH];
__device__ float g_sc[BB * SS];
__device__ float g_wsm[BB * SS];
__device__ float g_xcat[BB * XS];                   // col0=dec_in, 1..512=ctx, 513..543=0
__device__ float g_decin[BB];
__device__ float g_hist[BB];

// grid-wide barrier state
__device__ unsigned int g_bar_count = 0;
__device__ volatile unsigned int g_bar_gen = 0;

__device__ __forceinline__ void grid_barrier() {
    __syncthreads();
    if (threadIdx.x == 0) {
        __threadfence();
        unsigned int gen = g_bar_gen;
        if (atomicAdd(&g_bar_count, 1u) == NB - 1u) {
            g_bar_count = 0;
            __threadfence();
            g_bar_gen = gen + 1u;
        } else {
            while (g_bar_gen == gen) { __nanosleep(32); }
        }
        __threadfence();
    }
    __syncthreads();
}

__device__ __forceinline__ float fast_tanh(float x) {
    float y;
    asm("tanh.approx.f32 %0, %1;" : "=f"(y) : "f"(x));
    return y;
}
__device__ __forceinline__ float sigf(float x) {
    return __fdividef(1.f, 1.f + __expf(-x));
}
__device__ __forceinline__ float tanhg(float x) {
    return 1.f - __fdividef(2.f, __expf(2.f * x) + 1.f);
}
__device__ __forceinline__ float to_tf32(float x) {
    float y;
    asm("cvt.rna.tf32.f32 %0, %1;" : "=f"(y) : "f"(x));
    return y;
}

// ---------------- bulk copy + mbarrier primitives ----------------
__device__ __forceinline__ void bulk128(uint32_t dst, const float* src, uint32_t mbar) {
    asm volatile(
        "cp.async.bulk.shared::cluster.global.mbarrier::complete_tx::bytes "
        "[%0], [%1], 128, [%2];"
        :: "r"(dst), "l"(src), "r"(mbar) : "memory");
}
__device__ __forceinline__ void mb_init(uint32_t addr, unsigned count) {
    asm volatile("mbarrier.init.shared.b64 [%0], %1;" :: "r"(addr), "r"(count) : "memory");
}
__device__ __forceinline__ void mb_expect(uint32_t addr, unsigned bytes) {
    asm volatile("mbarrier.arrive.expect_tx.shared.b64 _, [%0], %1;"
                 :: "r"(addr), "r"(bytes) : "memory");
}
__device__ __forceinline__ void mb_wait(uint32_t addr, unsigned ph) {
    unsigned done = 0;
    while (!done) {
        asm volatile(
            "{\n\t.reg .pred p;\n\t"
            "mbarrier.try_wait.parity.acquire.cta.shared::cta.b64 p, [%1], %2, 0x989680;\n\t"
            "selp.b32 %0, 1, 0, p;\n\t}"
            : "=r"(done) : "r"(addr), "r"(ph) : "memory");
    }
}

// ---------------- fused prep ----------------
// n' = 4j+q maps to original row n = q*HH + j. Weights stored tf32-rounded.
__device__ __forceinline__ void interleave_region(
    float* __restrict__ dst, const float* __restrict__ Wa, int Ka,
    const float* __restrict__ Wb, int Kb, int base, int stride) {
    int Kt = Ka + Kb;
    int total = GG * Kt;
    for (int idx = base; idx < total; idx += stride) {
        int np = idx / Kt;
        int k = idx - np * Kt;
        int q = np & 3;
        int j = np >> 2;
        int n = q * HH + j;
        float v;
        if (k < Ka) v = Wa[(size_t)n * Ka + k];
        else        v = Wb[(size_t)n * Kb + (k - Ka)];
        dst[idx] = to_tf32(v);
    }
}

// Wd0: [0,513)=dw0, [513,544)=0, [544,1056)=du0
__device__ __forceinline__ void interleave_pad_wd0(
    float* __restrict__ dst, const float* __restrict__ Wa,
    const float* __restrict__ Wb, int base, int stride) {
    int total = GG * WD0K;
    for (int idx = base; idx < total; idx += stride) {
        int np = idx / WD0K;
        int k = idx - np * WD0K;
        int q = np & 3;
        int j = np >> 2;
        int n = q * HH + j;
        float v = 0.f;
        if (k < 513)      v = Wa[(size_t)n * 513 + k];
        else if (k >= XS) v = Wb[(size_t)n * HH + (k - XS)];
        dst[idx] = to_tf32(v);
    }
}

__global__ void prep_all(
    const float* __restrict__ src,
    const float* __restrict__ ew0, const float* __restrict__ eu0,
    const float* __restrict__ ebi0, const float* __restrict__ ebh0,
    const float* __restrict__ ew1, const float* __restrict__ eu1,
    const float* __restrict__ ebi1, const float* __restrict__ ebh1,
    const float* __restrict__ dw0, const float* __restrict__ du0,
    const float* __restrict__ dbi0, const float* __restrict__ dbh0,
    const float* __restrict__ dw1, const float* __restrict__ du1,
    const float* __restrict__ dbi1, const float* __restrict__ dbh1,
    const float* __restrict__ attn_W)
{
    int base = blockIdx.x * blockDim.x + threadIdx.x;
    int stride = gridDim.x * blockDim.x;

    interleave_region(g_W0, ew0, DD, eu0, HH, base, stride);
    interleave_region(g_W1, ew1, HH, eu1, HH, base, stride);
    interleave_pad_wd0(g_Wd0, dw0, du0, base, stride);
    interleave_region(g_Wd1, dw1, HH, du1, HH, base, stride);

    for (int i = base; i < HH * 2 * HH; i += stride) g_attnW[i] = to_tf32(attn_W[i]);
    for (int i = base; i < BB * SS * DD; i += stride) g_srcr[i] = to_tf32(src[i]);

    for (int np = base; np < GG; np += stride) {
        int q = np & 3;
        int j = np >> 2;
        int n = q * HH + j;
        g_b0[np] = ebi0[n] + ebh0[n];
        g_b1[np] = ebi1[n] + ebh1[n];
        g_bd0[np] = dbi0[n] + dbh0[n];
        g_bd1[np] = dbi1[n] + dbh1[n];
    }
    for (int i = base; i < BB * HH; i += stride) {
        g_h0[0][i] = 0.f; g_h1[0][i] = 0.f; g_c0[i] = 0.f; g_c1[i] = 0.f;
    }
    for (int i = base; i < BB * XS; i += stride) g_xcat[i] = 0.f;
    for (int i = base; i < BB; i += stride) {
        size_t o = (size_t)i * SS * DD + (size_t)(SS - 1) * DD;
        g_decin[i] = src[o + (DD - 1)];   // src[:, -1, -1]
        g_hist[i]  = src[o + (DD - 15)];  // src[:, -1, -15]
    }
}

// ---------------- wmma tf32 GEMM core, cp.async.bulk 4-stage pipeline --------
// Tile 64(m) x 64(n). K chunks of 32 (all K1 splits are multiples of 32).
// Staging per round: 128 row-bulks of 128B (A rows tid<64, W rows tid>=64)
// into padded 36-float-stride rows; mbarrier per stage tracks 16384 tx bytes.
// Global chunk counter (gctr) carries mbarrier phase across GEMM calls.
// 16 warps: 4(m) x 2(n) x 2(k-split); partial C tiles summed in epilogue.
// dyn smem (floats): 4 stages x (A 64x36 | W 64x36) = 4 x 4608.
// C partials alias stages 0/1 after drain: C0 @ 0, C1 @ 4608 (64x68 each).
typedef wmma::fragment<wmma::matrix_a, 16, 16, 8, wmma::precision::tf32, wmma::row_major> AFrag;
typedef wmma::fragment<wmma::matrix_b, 16, 16, 8, wmma::precision::tf32, wmma::col_major> BFrag;
typedef wmma::fragment<wmma::accumulator, 16, 16, 8, float> CFrag;

__device__ __forceinline__ void gemm_core_tf32(
    int bn, int bm,
    const float* __restrict__ A1, int lda1, int K1,
    const float* __restrict__ A2, int lda2, int K2,
    const float* __restrict__ W, int ldw,
    float* __restrict__ smem, uint32_t mbb, unsigned& gctr)
{
    const int tid = threadIdx.x;
    const int warp = tid >> 5;
    const int wm = warp & 3;          // 16-row group
    const int wn = (warp >> 2) & 1;   // 32-col group
    const int wk = warp >> 3;         // k8 half
    const int nck = (K1 + K2) >> 5;
    const unsigned g = gctr;
    const uint32_t sbase = (uint32_t)__cvta_generic_to_shared(smem);

    CFrag acc[2];
    wmma::fill_fragment(acc[0], 0.f);
    wmma::fill_fragment(acc[1], 0.f);

#define ISSUE(GCK)                                                             \
    {                                                                          \
        int k0 = ((int)((GCK) - g)) << 5;                                      \
        int r = tid & 63;                                                      \
        const float* srcp;                                                     \
        if (tid < 64)                                                          \
            srcp = (k0 < K1) ? A1 + (size_t)(bm + r) * lda1 + k0               \
                             : A2 + (size_t)(bm + r) * lda2 + (k0 - K1);       \
        else                                                                   \
            srcp = W + (size_t)(bn + r) * ldw + k0;                            \
        uint32_t dst = sbase + ((GCK) & 3u) * 18432u                           \
                     + (tid < 64 ? 0u : 9216u) + (uint32_t)r * 144u;           \
        bulk128(dst, srcp, mbb + ((GCK) & 3u) * 8u);                           \
    }

    // prologue: expect (tid 0) strictly before bulks (tid<128)
    if (tid == 0) {
        for (int s = 0; s < 3 && s < nck; s++)
            mb_expect(mbb + ((g + s) & 3u) * 8u, 16384u);
    }
    __syncthreads();
    if (tid < 128) {
        for (int s = 0; s < 3 && s < nck; s++) ISSUE(g + s);
    }

    for (int ck = 0; ck < nck; ck++) {
        unsigned GC = g + ck;
        mb_wait(mbb + (GC & 3u) * 8u, (GC >> 2) & 1u);
        if (tid == 0 && ck + 3 < nck)
            mb_expect(mbb + ((GC + 3) & 3u) * 8u, 16384u);
        const float* Ab = smem + (GC & 3u) * 4608;
        const float* Wb = Ab + 2304;
#pragma unroll
        for (int kh = 0; kh < 2; kh++) {
            int k8 = wk * 2 + kh;
            AFrag af;
            wmma::load_matrix_sync(af, &Ab[(wm * 16) * 36 + k8 * 8], 36);
            BFrag bf0, bf1;
            wmma::load_matrix_sync(bf0, &Wb[(wn * 32) * 36 + k8 * 8], 36);
            wmma::load_matrix_sync(bf1, &Wb[(wn * 32 + 16) * 36 + k8 * 8], 36);
            wmma::mma_sync(acc[0], af, bf0, acc[0]);
            wmma::mma_sync(acc[1], af, bf1, acc[1]);
        }
        __syncthreads();   // all warps done with stage GC (and GC-1) before reuse
        if (ck + 3 < nck && tid < 128) ISSUE(GC + 3);
    }
#undef ISSUE
    gctr = g + (unsigned)nck;

    // last loop iteration ended with __syncthreads -> safe to alias C onto stages
    float* Cb = smem + wk * 4608;      // C0 @ 0, C1 @ 4608
    wmma::store_matrix_sync(Cb + (wm * 16) * 68 + wn * 32, acc[0], 68, wmma::mem_row_major);
    wmma::store_matrix_sync(Cb + (wm * 16) * 68 + wn * 32 + 16, acc[1], 68, wmma::mem_row_major);
    __syncthreads();
}

// ---------------- tile GEMM + fused LSTM cell ----------------
__device__ __forceinline__ void gemm_lstm_tile(
    int tn, int tm,
    const float* __restrict__ A1, int lda1, int K1,
    const float* __restrict__ A2, int lda2, int K2,
    const float* __restrict__ W, int ldw,
    const float* __restrict__ bias,
    float* __restrict__ c_state,
    float* __restrict__ h_out,
    float* __restrict__ h_extra_r,
    float* __restrict__ h_extra_f, size_t extra_stride,
    float* __restrict__ smem, uint32_t mbb, unsigned& gctr)
{
    const int bn = tn * 64;
    const int bm = tm * 64;
    gemm_core_tf32(bn, bm, A1, lda1, K1, A2, lda2, K2, W, ldw, smem, mbb, gctr);
    const float* C0 = smem;
    const float* C1 = smem + 4608;

    const int tid = threadIdx.x;
#pragma unroll
    for (int t = 0; t < 2; t++) {
        int idx = tid + t * TPB;
        int r = idx >> 4;          // row in tile (batch)
        int jj = idx & 15;         // gate-quad within tile
        int b = bm + r;
        int ncol = bn + 4 * jj;
        int j = ncol >> 2;
        int o = r * 68 + 4 * jj;
        float gi = sigf(C0[o + 0] + C1[o + 0] + bias[ncol + 0]);
        float gf = sigf(C0[o + 1] + C1[o + 1] + bias[ncol + 1]);
        float gg = tanhg(C0[o + 2] + C1[o + 2] + bias[ncol + 2]);
        float go = sigf(C0[o + 3] + C1[o + 3] + bias[ncol + 3]);
        float c = gf * c_state[b * HH + j] + gi * gg;
        c_state[b * HH + j] = c;
        float hf = go * tanhg(c);           // full precision h
        float hr = to_tf32(hf);             // rounded (GEMM operand form)
        h_out[b * HH + j] = hr;
        if (h_extra_r) h_extra_r[(size_t)b * extra_stride + j] = hr;
        if (h_extra_f) h_extra_f[(size_t)b * extra_stride + j] = hf;
    }
    __syncthreads();
}

// ---------------- plain tile GEMM: C[m,n] = sum_k A[m,k]*W[n,k] (+bias) ------
__device__ __forceinline__ void gemm_bias_tile(
    int tn, int tm,
    const float* __restrict__ A, int lda,
    const float* __restrict__ W, int ldw,
    const float* __restrict__ bias,
    float* __restrict__ C, int N, int K,
    float* __restrict__ smem, uint32_t mbb, unsigned& gctr)
{
    const int bn = tn * 64;
    const int bm = tm * 64;
    gemm_core_tf32(bn, bm, A, lda, K, A, lda, 0, W, ldw, smem, mbb, gctr);
    const float* C0 = smem;
    const float* C1 = smem + 4608;

    const int tid = threadIdx.x;
#pragma unroll
    for (int t = 0; t < 2; t++) {
        int idx = tid + t * TPB;
        int r = idx >> 4;
        int c4 = idx & 15;
        int m = bm + r;
        int n = bn + 4 * c4;
        int o = r * 68 + 4 * c4;
        float4 v0 = *(const float4*)&C0[o];
        float4 v1 = *(const float4*)&C1[o];
        float4 v = make_float4(v0.x + v1.x, v0.y + v1.y, v0.z + v1.z, v0.w + v1.w);
        if (bias) {
            float4 bv = *(const float4*)&bias[n];
            v.x += bv.x; v.y += bv.y; v.z += bv.z; v.w += bv.w;
        }
        *(float4*)&C[(size_t)m * N + n] = v;
    }
    __syncthreads();
}

// ---------------- persistent mega-kernel ----------------
__global__ __launch_bounds__(TPB) void mega(
    const float* __restrict__ attn_b,
    const float* __restrict__ v_W,
    const float* __restrict__ fc_W,
    const float* __restrict__ fc_b,
    float* __restrict__ out)
{
    extern __shared__ __align__(16) float dyn[];   // 4 x 4608 floats (73.7 KB)
    __shared__ float sm[1024];
    __shared__ __align__(8) unsigned long long mbar_s[4];

    const int bid = blockIdx.x;
    const int tid = threadIdx.x;
    const int tn = bid & 31;   // 32 n-tiles (N=2048)
    const int tm = bid >> 5;   // 4 m-tiles  (M=256)

    const uint32_t mbb = (uint32_t)__cvta_generic_to_shared(mbar_s);
    if (tid == 0) {
        for (int s = 0; s < 4; s++) mb_init(mbb + s * 8u, 1u);
        asm volatile("fence.proxy.async;" ::: "memory");
    }
    __syncthreads();
    unsigned gctr = 0;   // global chunk counter (mbarrier phase), CTA-uniform

    // ---------------- encoder: 512 steps, ONE grid barrier per step ----------------
    for (int t = 0; t < SS; t++) {
        int p = t & 1;
        gemm_lstm_tile(tn, tm, g_srcr + t * DD, SS * DD, DD,
                       g_h0[p], HH, HH, g_W0, 544, g_b0,
                       g_c0, g_h0[p ^ 1], nullptr, nullptr, 0, dyn, mbb, gctr);
        grid_barrier();  // h0(t) complete; L1(t) and L0(t+1) are conflict-free after
        gemm_lstm_tile(tn, tm, g_h0[p ^ 1], HH, HH,
                       g_h1[p], HH, HH, g_W1, 1024, g_b1,
                       g_c1, g_h1[p ^ 1],
                       g_enc_outs_r + (size_t)t * HH,
                       g_enc_outs + (size_t)t * HH, (size_t)SS * HH, dyn, mbb, gctr);
    }
    grid_barrier();  // enc_outs + final states complete

    // ---------------- enc_proj = enc_outs_r @ W_enc^T + attn_b ----------------
    for (int tt = bid; tt < 16384; tt += NB) {
        gemm_bias_tile(tt & 7, tt >> 3, g_enc_outs_r, HH, g_attnW, 2 * HH,
                       attn_b, g_enc_proj, HH, HH, dyn, mbb, gctr);
    }
    grid_barrier();

    // ---------------- decoder: 24 steps ----------------
    for (int it = 0; it < PLEN; it++) {
        int p = it & 1;

        // A: dp = h1 @ W_dec^T   (8 x 4 = 32 tiles)
        if (bid < 32) {
            gemm_bias_tile(bid & 7, bid >> 3, g_h1[p], HH, g_attnW + HH, 2 * HH,
                           nullptr, g_dp, HH, HH, dyn, mbb, gctr);
        }
        grid_barrier();

        // B: scores[b,s] = sum_h v[h]*tanh(ep[b,s,h]+dp[b,h]) — 2 b per block
        {
            int warp = tid >> 5, lane = tid & 31;
#pragma unroll 1
            for (int bb = 0; bb < 2; bb++) {
                int b = bid * 2 + bb;
                for (int i = tid; i < HH; i += TPB) {
                    sm[i] = g_dp[b * HH + i];
                    sm[512 + i] = v_W[i];
                }
                __syncthreads();
                const float* ep = g_enc_proj + (size_t)b * SS * HH;
                for (int s = warp; s < SS; s += 16) {
                    const float* row = ep + (size_t)s * HH;
                    float acc = 0.f;
#pragma unroll
                    for (int h0 = 0; h0 < 4; h0++) {
                        int h = h0 * 128 + lane * 4;
                        float4 r = *(const float4*)&row[h];
                        float4 d = *(const float4*)&sm[h];
                        float4 v = *(const float4*)&sm[512 + h];
                        acc += v.x * fast_tanh(r.x + d.x)
                             + v.y * fast_tanh(r.y + d.y)
                             + v.z * fast_tanh(r.z + d.z)
                             + v.w * fast_tanh(r.w + d.w);
                    }
#pragma unroll
                    for (int off = 16; off > 0; off >>= 1)
                        acc += __shfl_down_sync(0xffffffffu, acc, off);
                    if (lane == 0) g_sc[b * SS + s] = acc;
                }
                __syncthreads();
            }
        }
        grid_barrier();

        // C: softmax over s — 2 b per block
        {
#pragma unroll 1
            for (int bb = 0; bb < 2; bb++) {
                int b = bid * 2 + bb;
                float m = -1e30f;
                for (int s = tid; s < SS; s += TPB) m = fmaxf(m, g_sc[b * SS + s]);
                sm[tid] = m; __syncthreads();
                for (int off = TPB / 2; off > 0; off >>= 1) {
                    if (tid < off) sm[tid] = fmaxf(sm[tid], sm[tid + off]);
                    __syncthreads();
                }
                m = sm[0]; __syncthreads();
                float sum = 0.f;
                for (int s = tid; s < SS; s += TPB) {
                    float e = __expf(g_sc[b * SS + s] - m);
                    g_wsm[b * SS + s] = e;
                    sum += e;
                }
                sm[tid] = sum; __syncthreads();
                for (int off = TPB / 2; off > 0; off >>= 1) {
                    if (tid < off) sm[tid] += sm[tid + off];
                    __syncthreads();
                }
                float inv = 1.f / sm[0]; __syncthreads();
                for (int s = tid; s < SS; s += TPB) g_wsm[b * SS + s] *= inv;
            }
        }
        grid_barrier();

        // D: context (from FULL fp32 enc_outs) -> xcat rounded; xcat[:,0] = dec_in
        {
#pragma unroll 1
            for (int bb = 0; bb < 2; bb++) {
                int b = bid * 2 + bb;
                for (int i = tid; i < SS; i += TPB) sm[i] = g_wsm[b * SS + i];
                __syncthreads();
                const float* base = g_enc_outs + (size_t)b * SS * HH;
                float a0 = 0.f;
#pragma unroll 4
                for (int s = 0; s < SS; s++) {
                    a0 += sm[s] * base[(size_t)s * HH + tid];
                }
                g_xcat[b * XS + 1 + tid] = to_tf32(a0);
                if (tid == 0) g_xcat[b * XS] = to_tf32(g_decin[b]);
                __syncthreads();
            }
        }
        grid_barrier();

        // E: decoder LSTM layer 0 (K = 544 + 512, chunk-aligned)
        gemm_lstm_tile(tn, tm, g_xcat, XS, XS,
                       g_h0[p], HH, HH, g_Wd0, WD0K, g_bd0,
                       g_c0, g_h0[p ^ 1], nullptr, nullptr, 0, dyn, mbb, gctr);
        grid_barrier();

        // F: decoder LSTM layer 1 (K = 1024); full h copy for stage G
        gemm_lstm_tile(tn, tm, g_h0[p ^ 1], HH, HH,
                       g_h1[p], HH, HH, g_Wd1, 1024, g_bd1,
                       g_c1, g_h1[p ^ 1], nullptr, g_h1f, HH, dyn, mbb, gctr);
        grid_barrier();

        // G: pred = h1f (FULL fp32) . fc_W  (16 blocks x 16 warps = 256 b)
        if (bid < 16) {
            int warp = tid >> 5, lane = tid & 31;
            int b = bid * 16 + warp;
            const float* h1r = g_h1f + b * HH;
            float acc = 0.f;
            for (int h = lane; h < HH; h += 32) acc += h1r[h] * fc_W[h];
#pragma unroll
            for (int off = 16; off > 0; off >>= 1)
                acc += __shfl_down_sync(0xffffffffu, acc, off);
            if (lane == 0) {
                float pred = acc + fc_b[0];
                out[b * PLEN + it] = pred;
                g_decin[b] = 0.8f * pred + 0.2f * g_hist[b];
            }
        }
        // G(t)'s decin write is ordered before D(t+1)'s read by the barriers
        // after A(t+1); dp overwrite in A(t+1) is ordered after B(t).
    }
}

// ---------------- launch ----------------
extern "C" void kernel_launch(void* const* d_in, const int* in_sizes, int n_in,
                              void* d_out, int out_size) {
    (void)in_sizes; (void)n_in; (void)out_size;
    const float* src    = (const float*)d_in[0];
    const float* ew0    = (const float*)d_in[1];
    const float* eu0    = (const float*)d_in[2];
    const float* ebi0   = (const float*)d_in[3];
    const float* ebh0   = (const float*)d_in[4];
    const float* ew1    = (const float*)d_in[5];
    const float* eu1    = (const float*)d_in[6];
    const float* ebi1   = (const float*)d_in[7];
    const float* ebh1   = (const float*)d_in[8];
    const float* dw0    = (const float*)d_in[9];
    const float* du0    = (const float*)d_in[10];
    const float* dbi0   = (const float*)d_in[11];
    const float* dbh0   = (const float*)d_in[12];
    const float* dw1    = (const float*)d_in[13];
    const float* du1    = (const float*)d_in[14];
    const float* dbi1   = (const float*)d_in[15];
    const float* dbh1   = (const float*)d_in[16];
    const float* attn_W = (const float*)d_in[17];
    const float* attn_b = (const float*)d_in[18];
    const float* v_W    = (const float*)d_in[19];
    const float* fc_W   = (const float*)d_in[20];
    const float* fc_b   = (const float*)d_in[21];
    float* out = (float*)d_out;

    static int smem_set = 0;
    const int dyn_bytes = 4 * 4608 * 4;   // 73728
    if (!smem_set) {
        cudaFuncSetAttribute(mega, cudaFuncAttributeMaxDynamicSharedMemorySize,
                             dyn_bytes);
        smem_set = 1;
    }

    prep_all<<<2048, 256>>>(src, ew0, eu0, ebi0, ebh0, ew1, eu1, ebi1, ebh1,
                            dw0, du0, dbi0, dbh0, dw1, du1, dbi1, dbh1, attn_W);
    mega<<<NB, TPB, dyn_bytes>>>(attn_b, v_W, fc_W, fc_b, out);
}

// round 16
// speedup vs baseline: 1.9544x; 1.9544x over previous
#include <cuda_runtime.h>
#include <mma.h>
#include <math.h>
#include <stdint.h>

using namespace nvcuda;

#define BB 256
#define SS 512
#define DD 32
#define HH 512
#define GG 2048   // 4*HH
#define PLEN 24
#define NB 256    // persistent blocks, 2 per SM (all co-resident: 256 <= 148*2)
#define TPB 256   // threads per block (8 warps)

#define XS 544    // xcat padded stride (544 = 17*32)
#define WD0K 1056 // Wd0 padded K (544 + 512)

// smem per stage: A 64x36 + W 32x36 = 3456 floats; 4 stages = 55296 B
#define STG 3456

// ---------------- scratch (__device__ globals; no allocation) ----------------
__device__ float g_enc_outs[BB * SS * HH];          // FULL fp32 h (stage D reads)
__device__ float g_enc_outs_r[BB * SS * HH];        // tf32-rounded h (enc_proj GEMM)
__device__ float g_enc_proj[BB * SS * HH];          // full fp32
__device__ float g_srcr[BB * SS * DD];              // tf32-rounded src copy
__device__ float g_attnW[HH * 2 * HH];              // tf32-rounded attn_W copy
__device__ float g_h0[2][BB * HH];                  // rounded (GEMM operand)
__device__ float g_h1[2][BB * HH];                  // rounded (GEMM operand)
__device__ float g_h1f[BB * HH];                    // FULL fp32 decoder h1 (stage G)
__device__ float g_c0[BB * HH];
__device__ float g_c1[BB * HH];
__device__ float g_W0[GG * 544];                    // [ew0 | eu0], gate-interleaved, tf32
__device__ float g_W1[GG * 1024];                   // [ew1 | eu1], tf32
__device__ float g_Wd0[GG * WD0K];                  // [dw0 | pad | du0], tf32
__device__ float g_Wd1[GG * 1024];                  // [dw1 | du1], tf32
__device__ float g_b0[GG], g_b1[GG], g_bd0[GG], g_bd1[GG];
__device__ float g_dp[BB * HH];
__device__ float g_sc[BB * SS];
__device__ float g_wsm[BB * SS];
__device__ float g_xcat[BB * XS];                   // col0=dec_in, 1..512=ctx, 513..543=0
__device__ float g_decin[BB];
__device__ float g_hist[BB];

// grid-wide barrier state
__device__ unsigned int g_bar_count = 0;
__device__ volatile unsigned int g_bar_gen = 0;

__device__ __forceinline__ void grid_barrier() {
    __syncthreads();
    if (threadIdx.x == 0) {
        __threadfence();
        unsigned int gen = g_bar_gen;
        if (atomicAdd(&g_bar_count, 1u) == NB - 1u) {
            g_bar_count = 0;
            __threadfence();
            g_bar_gen = gen + 1u;
        } else {
            while (g_bar_gen == gen) { __nanosleep(32); }
        }
        __threadfence();
    }
    __syncthreads();
}

__device__ __forceinline__ float fast_tanh(float x) {
    float y;
    asm("tanh.approx.f32 %0, %1;" : "=f"(y) : "f"(x));
    return y;
}
__device__ __forceinline__ float sigf(float x) {
    return __fdividef(1.f, 1.f + __expf(-x));
}
__device__ __forceinline__ float tanhg(float x) {
    return 1.f - __fdividef(2.f, __expf(2.f * x) + 1.f);
}
__device__ __forceinline__ float to_tf32(float x) {
    float y;
    asm("cvt.rna.tf32.f32 %0, %1;" : "=f"(y) : "f"(x));
    return y;
}

__device__ __forceinline__ void cp16(uint32_t dst, const float* src) {
    asm volatile("cp.async.cg.shared.global [%0], [%1], 16;" :: "r"(dst), "l"(src));
}
#define CP_COMMIT() asm volatile("cp.async.commit_group;")
#define CP_WAIT2()  asm volatile("cp.async.wait_group 2;")

// ---------------- fused prep ----------------
// n' = 4j+q maps to original row n = q*HH + j. Weights stored tf32-rounded.
__device__ __forceinline__ void interleave_region(
    float* __restrict__ dst, const float* __restrict__ Wa, int Ka,
    const float* __restrict__ Wb, int Kb, int base, int stride) {
    int Kt = Ka + Kb;
    int total = GG * Kt;
    for (int idx = base; idx < total; idx += stride) {
        int np = idx / Kt;
        int k = idx - np * Kt;
        int q = np & 3;
        int j = np >> 2;
        int n = q * HH + j;
        float v;
        if (k < Ka) v = Wa[(size_t)n * Ka + k];
        else        v = Wb[(size_t)n * Kb + (k - Ka)];
        dst[idx] = to_tf32(v);
    }
}

// Wd0: [0,513)=dw0, [513,544)=0, [544,1056)=du0
__device__ __forceinline__ void interleave_pad_wd0(
    float* __restrict__ dst, const float* __restrict__ Wa,
    const float* __restrict__ Wb, int base, int stride) {
    int total = GG * WD0K;
    for (int idx = base; idx < total; idx += stride) {
        int np = idx / WD0K;
        int k = idx - np * WD0K;
        int q = np & 3;
        int j = np >> 2;
        int n = q * HH + j;
        float v = 0.f;
        if (k < 513)      v = Wa[(size_t)n * 513 + k];
        else if (k >= XS) v = Wb[(size_t)n * HH + (k - XS)];
        dst[idx] = to_tf32(v);
    }
}

__global__ void prep_all(
    const float* __restrict__ src,
    const float* __restrict__ ew0, const float* __restrict__ eu0,
    const float* __restrict__ ebi0, const float* __restrict__ ebh0,
    const float* __restrict__ ew1, const float* __restrict__ eu1,
    const float* __restrict__ ebi1, const float* __restrict__ ebh1,
    const float* __restrict__ dw0, const float* __restrict__ du0,
    const float* __restrict__ dbi0, const float* __restrict__ dbh0,
    const float* __restrict__ dw1, const float* __restrict__ du1,
    const float* __restrict__ dbi1, const float* __restrict__ dbh1,
    const float* __restrict__ attn_W)
{
    int base = blockIdx.x * blockDim.x + threadIdx.x;
    int stride = gridDim.x * blockDim.x;

    interleave_region(g_W0, ew0, DD, eu0, HH, base, stride);
    interleave_region(g_W1, ew1, HH, eu1, HH, base, stride);
    interleave_pad_wd0(g_Wd0, dw0, du0, base, stride);
    interleave_region(g_Wd1, dw1, HH, du1, HH, base, stride);

    for (int i = base; i < HH * 2 * HH; i += stride) g_attnW[i] = to_tf32(attn_W[i]);
    for (int i = base; i < BB * SS * DD; i += stride) g_srcr[i] = to_tf32(src[i]);

    for (int np = base; np < GG; np += stride) {
        int q = np & 3;
        int j = np >> 2;
        int n = q * HH + j;
        g_b0[np] = ebi0[n] + ebh0[n];
        g_b1[np] = ebi1[n] + ebh1[n];
        g_bd0[np] = dbi0[n] + dbh0[n];
        g_bd1[np] = dbi1[n] + dbh1[n];
    }
    for (int i = base; i < BB * HH; i += stride) {
        g_h0[0][i] = 0.f; g_h1[0][i] = 0.f; g_c0[i] = 0.f; g_c1[i] = 0.f;
    }
    for (int i = base; i < BB * XS; i += stride) g_xcat[i] = 0.f;
    for (int i = base; i < BB; i += stride) {
        size_t o = (size_t)i * SS * DD + (size_t)(SS - 1) * DD;
        g_decin[i] = src[o + (DD - 1)];   // src[:, -1, -1]
        g_hist[i]  = src[o + (DD - 15)];  // src[:, -1, -15]
    }
}

// ---------------- wmma tf32 GEMM core, cp.async 4-stage pipeline --------------
// Tile 64(m) x 32(n). K chunks of 32 (all K1 splits multiples of 32).
// 8 warps: 4(m) x 2(k-split); each warp: two 16x16 acc frags (cols 0-15,16-31)
// over half the k8 sub-steps; partial C tiles summed in the epilogue.
// dyn smem: 4 stages x (A 64x36 | W 32x36) = 4 x 3456 floats (55.3 KB).
// C partials alias after drain: C0 @ 0, C1 @ 2304 (64x36 each, 64x32 valid).
typedef wmma::fragment<wmma::matrix_a, 16, 16, 8, wmma::precision::tf32, wmma::row_major> AFrag;
typedef wmma::fragment<wmma::matrix_b, 16, 16, 8, wmma::precision::tf32, wmma::col_major> BFrag;
typedef wmma::fragment<wmma::accumulator, 16, 16, 8, float> CFrag;

__device__ __forceinline__ void gemm_core_tf32(
    int bn, int bm,
    const float* __restrict__ A1, int lda1, int K1,
    const float* __restrict__ A2, int lda2, int K2,
    const float* __restrict__ W, int ldw,
    float* __restrict__ smem)
{
    const int tid = threadIdx.x;
    const int warp = tid >> 5;
    const int wm = warp & 3;          // 16-row group
    const int wk = warp >> 2;         // k8 half
    const int nck = (K1 + K2) >> 5;
    const int rowA = tid >> 3;        // 0..31 (A rows in 2 passes)
    const int seg = tid & 7;          // 16B segment within 32-col chunk
    const uint32_t sbase = (uint32_t)__cvta_generic_to_shared(smem);

    CFrag acc[2];
    wmma::fill_fragment(acc[0], 0.f);
    wmma::fill_fragment(acc[1], 0.f);

#define ISSUE(CK)                                                              \
    {                                                                          \
        int k0 = (CK) << 5;                                                    \
        uint32_t sb = sbase + (uint32_t)(((CK) & 3) * STG) * 4u;               \
        const float* Abase = (k0 < K1) ? A1 : A2;                              \
        int lda = (k0 < K1) ? lda1 : lda2;                                     \
        int kof = (k0 < K1) ? k0 : (k0 - K1);                                  \
        /* t2=0,1: A rows 0..31, 32..63 */                                     \
        cp16(sb + (uint32_t)((rowA * 36 + seg * 4) * 4),                       \
             Abase + (size_t)(bm + rowA) * lda + kof + seg * 4);               \
        cp16(sb + (uint32_t)(((rowA + 32) * 36 + seg * 4) * 4),                \
             Abase + (size_t)(bm + rowA + 32) * lda + kof + seg * 4);          \
        /* t2=2: W rows 0..31 */                                               \
        cp16(sb + (uint32_t)((2304 + rowA * 36 + seg * 4) * 4),                \
             W + (size_t)(bn + rowA) * ldw + k0 + seg * 4);                    \
    }

    ISSUE(0); CP_COMMIT();
    ISSUE(1); CP_COMMIT();
    ISSUE(2); CP_COMMIT();

    for (int ck = 0; ck < nck; ck++) {
        CP_WAIT2();          // group ck complete (own copies)
        __syncthreads();     // publish all threads' copies; also guards reuse
        if (ck + 3 < nck) ISSUE(ck + 3);
        CP_COMMIT();         // always commit (empty groups keep count uniform)
        const float* Ab = smem + (ck & 3) * STG;
        const float* Wb = Ab + 2304;
#pragma unroll
        for (int kh = 0; kh < 2; kh++) {
            int k8 = wk * 2 + kh;
            AFrag af;
            wmma::load_matrix_sync(af, &Ab[(wm * 16) * 36 + k8 * 8], 36);
            BFrag bf0, bf1;
            wmma::load_matrix_sync(bf0, &Wb[k8 * 8], 36);
            wmma::load_matrix_sync(bf1, &Wb[16 * 36 + k8 * 8], 36);
            wmma::mma_sync(acc[0], af, bf0, acc[0]);
            wmma::mma_sync(acc[1], af, bf1, acc[1]);
        }
    }
#undef ISSUE

    __syncthreads();   // all mma smem reads done before aliasing C onto stages
    float* Cb = smem + wk * 2304;      // C0 @ 0, C1 @ 2304
    wmma::store_matrix_sync(Cb + (wm * 16) * 36, acc[0], 36, wmma::mem_row_major);
    wmma::store_matrix_sync(Cb + (wm * 16) * 36 + 16, acc[1], 36, wmma::mem_row_major);
    __syncthreads();
}

// ---------------- tile GEMM + fused LSTM cell ----------------
__device__ __forceinline__ void gemm_lstm_tile(
    int tn, int tm,
    const float* __restrict__ A1, int lda1, int K1,
    const float* __restrict__ A2, int lda2, int K2,
    const float* __restrict__ W, int ldw,
    const float* __restrict__ bias,
    float* __restrict__ c_state,
    float* __restrict__ h_out,
    float* __restrict__ h_extra_r,
    float* __restrict__ h_extra_f, size_t extra_stride,
    float* __restrict__ smem)
{
    const int bn = tn * 32;
    const int bm = tm * 64;
    gemm_core_tf32(bn, bm, A1, lda1, K1, A2, lda2, K2, W, ldw, smem);
    const float* C0 = smem;
    const float* C1 = smem + 2304;

    const int tid = threadIdx.x;
    // 64 rows x 8 gate-quads = 512 work items
#pragma unroll
    for (int t = 0; t < 2; t++) {
        int idx = tid + t * TPB;
        int r = idx >> 3;          // row in tile (batch)
        int jj = idx & 7;          // gate-quad within tile
        int b = bm + r;
        int ncol = bn + 4 * jj;
        int j = ncol >> 2;
        int o = r * 36 + 4 * jj;
        float gi = sigf(C0[o + 0] + C1[o + 0] + bias[ncol + 0]);
        float gf = sigf(C0[o + 1] + C1[o + 1] + bias[ncol + 1]);
        float gg = tanhg(C0[o + 2] + C1[o + 2] + bias[ncol + 2]);
        float go = sigf(C0[o + 3] + C1[o + 3] + bias[ncol + 3]);
        float c = gf * c_state[b * HH + j] + gi * gg;
        c_state[b * HH + j] = c;
        float hf = go * tanhg(c);           // full precision h
        float hr = to_tf32(hf);             // rounded (GEMM operand form)
        h_out[b * HH + j] = hr;
        if (h_extra_r) h_extra_r[(size_t)b * extra_stride + j] = hr;
        if (h_extra_f) h_extra_f[(size_t)b * extra_stride + j] = hf;
    }
    __syncthreads();
}

// ---------------- plain tile GEMM: C[m,n] = sum_k A[m,k]*W[n,k] (+bias) ------
__device__ __forceinline__ void gemm_bias_tile(
    int tn, int tm,
    const float* __restrict__ A, int lda,
    const float* __restrict__ W, int ldw,
    const float* __restrict__ bias,
    float* __restrict__ C, int N, int K,
    float* __restrict__ smem)
{
    const int bn = tn * 32;
    const int bm = tm * 64;
    gemm_core_tf32(bn, bm, A, lda, K, A, lda, 0, W, ldw, smem);
    const float* C0 = smem;
    const float* C1 = smem + 2304;

    const int tid = threadIdx.x;
#pragma unroll
    for (int t = 0; t < 2; t++) {
        int idx = tid + t * TPB;
        int r = idx >> 3;
        int c4 = idx & 7;
        int m = bm + r;
        int n = bn + 4 * c4;
        int o = r * 36 + 4 * c4;
        float4 v0 = *(const float4*)&C0[o];
        float4 v1 = *(const float4*)&C1[o];
        float4 v = make_float4(v0.x + v1.x, v0.y + v1.y, v0.z + v1.z, v0.w + v1.w);
        if (bias) {
            float4 bv = *(const float4*)&bias[n];
            v.x += bv.x; v.y += bv.y; v.z += bv.z; v.w += bv.w;
        }
        *(float4*)&C[(size_t)m * N + n] = v;
    }
    __syncthreads();
}

// ---------------- persistent mega-kernel ----------------
__global__ __launch_bounds__(TPB, 2) void mega(
    const float* __restrict__ attn_b,
    const float* __restrict__ v_W,
    const float* __restrict__ fc_W,
    const float* __restrict__ fc_b,
    float* __restrict__ out)
{
    extern __shared__ __align__(16) float dyn[];   // 4 x 3456 floats (55.3 KB)
    __shared__ float sm[1024];

    const int bid = blockIdx.x;
    const int tid = threadIdx.x;
    const int tn = bid & 63;   // 64 n-tiles (N=2048, 32 each)
    const int tm = bid >> 6;   // 4 m-tiles  (M=256, 64 each)

    // ---------------- encoder: 512 steps, ONE grid barrier per step ----------------
    for (int t = 0; t < SS; t++) {
        int p = t & 1;
        gemm_lstm_tile(tn, tm, g_srcr + t * DD, SS * DD, DD,
                       g_h0[p], HH, HH, g_W0, 544, g_b0,
                       g_c0, g_h0[p ^ 1], nullptr, nullptr, 0, dyn);
        grid_barrier();  // h0(t) complete; L1(t) and L0(t+1) are conflict-free after
        gemm_lstm_tile(tn, tm, g_h0[p ^ 1], HH, HH,
                       g_h1[p], HH, HH, g_W1, 1024, g_b1,
                       g_c1, g_h1[p ^ 1],
                       g_enc_outs_r + (size_t)t * HH,
                       g_enc_outs + (size_t)t * HH, (size_t)SS * HH, dyn);
    }
    grid_barrier();  // enc_outs + final states complete

    // ---------------- enc_proj = enc_outs_r @ W_enc^T + attn_b ----------------
    // tiles: 2048(m) x 16(n) = 32768
    for (int tt = bid; tt < 32768; tt += NB) {
        gemm_bias_tile(tt & 15, tt >> 4, g_enc_outs_r, HH, g_attnW, 2 * HH,
                       attn_b, g_enc_proj, HH, HH, dyn);
    }
    grid_barrier();

    // ---------------- decoder: 24 steps ----------------
    for (int it = 0; it < PLEN; it++) {
        int p = it & 1;

        // A: dp = h1 @ W_dec^T   (16 x 4 = 64 tiles)
        if (bid < 64) {
            gemm_bias_tile(bid & 15, bid >> 4, g_h1[p], HH, g_attnW + HH, 2 * HH,
                           nullptr, g_dp, HH, HH, dyn);
        }
        grid_barrier();

        // B: scores[b,s] = sum_h v[h]*tanh(ep[b,s,h]+dp[b,h]) — 1 b per block
        {
            int warp = tid >> 5, lane = tid & 31;
            int b = bid;
            for (int i = tid; i < HH; i += TPB) {
                sm[i] = g_dp[b * HH + i];
                sm[512 + i] = v_W[i];
            }
            __syncthreads();
            const float* ep = g_enc_proj + (size_t)b * SS * HH;
            for (int s = warp; s < SS; s += 8) {
                const float* row = ep + (size_t)s * HH;
                float acc = 0.f;
#pragma unroll
                for (int h0 = 0; h0 < 4; h0++) {
                    int h = h0 * 128 + lane * 4;
                    float4 r = *(const float4*)&row[h];
                    float4 d = *(const float4*)&sm[h];
                    float4 v = *(const float4*)&sm[512 + h];
                    acc += v.x * fast_tanh(r.x + d.x)
                         + v.y * fast_tanh(r.y + d.y)
                         + v.z * fast_tanh(r.z + d.z)
                         + v.w * fast_tanh(r.w + d.w);
                }
#pragma unroll
                for (int off = 16; off > 0; off >>= 1)
                    acc += __shfl_down_sync(0xffffffffu, acc, off);
                if (lane == 0) g_sc[b * SS + s] = acc;
            }
            __syncthreads();
        }
        grid_barrier();

        // C: softmax over s — 1 b per block
        {
            int b = bid;
            float m = -1e30f;
            for (int s = tid; s < SS; s += TPB) m = fmaxf(m, g_sc[b * SS + s]);
            sm[tid] = m; __syncthreads();
            for (int off = TPB / 2; off > 0; off >>= 1) {
                if (tid < off) sm[tid] = fmaxf(sm[tid], sm[tid + off]);
                __syncthreads();
            }
            m = sm[0]; __syncthreads();
            float sum = 0.f;
            for (int s = tid; s < SS; s += TPB) {
                float e = __expf(g_sc[b * SS + s] - m);
                g_wsm[b * SS + s] = e;
                sum += e;
            }
            sm[tid] = sum; __syncthreads();
            for (int off = TPB / 2; off > 0; off >>= 1) {
                if (tid < off) sm[tid] += sm[tid + off];
                __syncthreads();
            }
            float inv = 1.f / sm[0]; __syncthreads();
            for (int s = tid; s < SS; s += TPB) g_wsm[b * SS + s] *= inv;
        }
        grid_barrier();

        // D: context (from FULL fp32 enc_outs) -> xcat rounded; xcat[:,0] = dec_in
        {
            int b = bid;
            for (int i = tid; i < SS; i += TPB) sm[i] = g_wsm[b * SS + i];
            __syncthreads();
            const float* base = g_enc_outs + (size_t)b * SS * HH;
            float a0 = 0.f, a1 = 0.f;
#pragma unroll 4
            for (int s = 0; s < SS; s++) {
                const float* r = base + (size_t)s * HH;
                a0 += sm[s] * r[tid];
                a1 += sm[s] * r[tid + 256];
            }
            g_xcat[b * XS + 1 + tid] = to_tf32(a0);
            g_xcat[b * XS + 1 + tid + 256] = to_tf32(a1);
            if (tid == 0) g_xcat[b * XS] = to_tf32(g_decin[b]);
            __syncthreads();
        }
        grid_barrier();

        // E: decoder LSTM layer 0 (K = 544 + 512, chunk-aligned)
        gemm_lstm_tile(tn, tm, g_xcat, XS, XS,
                       g_h0[p], HH, HH, g_Wd0, WD0K, g_bd0,
                       g_c0, g_h0[p ^ 1], nullptr, nullptr, 0, dyn);
        grid_barrier();

        // F: decoder LSTM layer 1 (K = 1024); full h copy for stage G
        gemm_lstm_tile(tn, tm, g_h0[p ^ 1], HH, HH,
                       g_h1[p], HH, HH, g_Wd1, 1024, g_bd1,
                       g_c1, g_h1[p ^ 1], nullptr, g_h1f, HH, dyn);
        grid_barrier();

        // G: pred = h1f (FULL fp32) . fc_W  (32 blocks x 8 warps = 256 b)
        if (bid < 32) {
            int warp = tid >> 5, lane = tid & 31;
            int b = bid * 8 + warp;
            const float* h1r = g_h1f + b * HH;
            float acc = 0.f;
            for (int h = lane; h < HH; h += 32) acc += h1r[h] * fc_W[h];
#pragma unroll
            for (int off = 16; off > 0; off >>= 1)
                acc += __shfl_down_sync(0xffffffffu, acc, off);
            if (lane == 0) {
                float pred = acc + fc_b[0];
                out[b * PLEN + it] = pred;
                g_decin[b] = 0.8f * pred + 0.2f * g_hist[b];
            }
        }
        // G(t)'s decin write is ordered before D(t+1)'s read by the barriers
        // after A(t+1); dp overwrite in A(t+1) is ordered after B(t).
    }
}

// ---------------- launch ----------------
extern "C" void kernel_launch(void* const* d_in, const int* in_sizes, int n_in,
                              void* d_out, int out_size) {
    (void)in_sizes; (void)n_in; (void)out_size;
    const float* src    = (const float*)d_in[0];
    const float* ew0    = (const float*)d_in[1];
    const float* eu0    = (const float*)d_in[2];
    const float* ebi0   = (const float*)d_in[3];
    const float* ebh0   = (const float*)d_in[4];
    const float* ew1    = (const float*)d_in[5];
    const float* eu1    = (const float*)d_in[6];
    const float* ebi1   = (const float*)d_in[7];
    const float* ebh1   = (const float*)d_in[8];
    const float* dw0    = (const float*)d_in[9];
    const float* du0    = (const float*)d_in[10];
    const float* dbi0   = (const float*)d_in[11];
    const float* dbh0   = (const float*)d_in[12];
    const float* dw1    = (const float*)d_in[13];
    const float* du1    = (const float*)d_in[14];
    const float* dbi1   = (const float*)d_in[15];
    const float* dbh1   = (const float*)d_in[16];
    const float* attn_W = (const float*)d_in[17];
    const float* attn_b = (const float*)d_in[18];
    const float* v_W    = (const float*)d_in[19];
    const float* fc_W   = (const float*)d_in[20];
    const float* fc_b   = (const float*)d_in[21];
    float* out = (float*)d_out;

    static int smem_set = 0;
    const int dyn_bytes = 4 * STG * 4;   // 55296
    if (!smem_set) {
        cudaFuncSetAttribute(mega, cudaFuncAttributeMaxDynamicSharedMemorySize,
                             dyn_bytes);
        smem_set = 1;
    }

    prep_all<<<2048, 256>>>(src, ew0, eu0, ebi0, ebh0, ew1, eu1, ebi1, ebh1,
                            dw0, du0, dbi0, dbh0, dw1, du1, dbi1, dbh1, attn_W);
    mega<<<NB, TPB, dyn_bytes>>>(attn_b, v_W, fc_W, fc_b, out);
}